// round 2
// baseline (speedup 1.0000x reference)
#include <cuda_runtime.h>
#include <cstdint>

// Fixed problem shape: stimuli [4,32,304,608,1] fp32, eye [4,32,2,3]
constexpr int H  = 304;
constexpr int W  = 608;
constexpr int HW = H * W;              // 184832
constexpr int NFRAMES = 128;           // 4*32
constexpr int GROUPS_PER_FRAME = HW / 4;  // W divisible by 4 -> aligned float4

__global__ __launch_bounds__(256) void warp_bilinear_kernel(
    const float* __restrict__ stimuli,
    const float* __restrict__ eye,
    float* __restrict__ out)
{
    const int n = blockIdx.y;
    const int g = blockIdx.x * blockDim.x + threadIdx.x;
    if (g >= GROUPS_PER_FRAME) return;

    const int p   = g * 4;
    const int row = p / W;
    const int col = p - row * W;

    const float* a = eye + (size_t)n * 6;
    const float a00 = __ldg(a + 0);
    const float a01 = __ldg(a + 1);
    const float a02 = __ldg(a + 2);
    const float a10 = __ldg(a + 3);
    const float a11 = __ldg(a + 4);
    const float a12 = __ldg(a + 5);

    // jnp.linspace(-1,1,H): step = fl32(2/(H-1)); y_t[j] = fl(-1 + fl(j*step));
    // endpoint: y_t[H-1] = 1.0 exactly.
    const float step_y = 2.0f / (float)(H - 1);
    const float yt = (row == H - 1)
                   ? 1.0f
                   : __fadd_rn(-1.0f, __fmul_rn((float)row, step_y));

    const float* __restrict__ img = stimuli + (size_t)n * HW;

    float4 res;
    float* rp = reinterpret_cast<float*>(&res);

    const float step_x = 2.0f / (float)(W - 1);

#pragma unroll
    for (int i = 0; i < 4; ++i) {
        const int c = col + i;
        const float xt = (c == W - 1)
                       ? 1.0f
                       : __fadd_rn(-1.0f, __fmul_rn((float)c, step_x));

        // einsum dot over j (k-order fmuladd chain):
        //   T = ((a0*x) fma a1*y) + a2, i.e. fadd(fmaf(a1, yt, fmul(a0, xt)), a2)
        const float Tx = __fadd_rn(__fmaf_rn(a01, yt, __fmul_rn(a00, xt)), a02);
        const float Ty = __fadd_rn(__fmaf_rn(a11, yt, __fmul_rn(a10, xt)), a12);

        // x = (T + 1) * (W/2), separate rounded ops
        const float x = __fmul_rn(__fadd_rn(Tx, 1.0f), (float)W * 0.5f);
        const float y = __fmul_rn(__fadd_rn(Ty, 1.0f), (float)H * 0.5f);

        int x0 = (int)floorf(x);
        int y0 = (int)floorf(y);
        int x1 = x0 + 1;
        int y1 = y0 + 1;
        x0 = min(max(x0, 0), W - 1);
        x1 = min(max(x1, 0), W - 1);
        y0 = min(max(y0, 0), H - 1);
        y1 = min(max(y1, 0), H - 1);

        const float Ia = __ldg(img + y0 * W + x0);
        const float Ib = __ldg(img + y1 * W + x0);
        const float Ic = __ldg(img + y0 * W + x1);
        const float Id = __ldg(img + y1 * W + x1);

        const float x0f = (float)x0, x1f = (float)x1;
        const float y0f = (float)y0, y1f = (float)y1;

        // weights: separately rounded subs and muls (no fma contraction)
        const float dx1 = __fsub_rn(x1f, x);   //  (x1f - x)
        const float dx0 = __fsub_rn(x, x0f);   //  (x - x0f)
        const float dy1 = __fsub_rn(y1f, y);   //  (y1f - y)
        const float dy0 = __fsub_rn(y, y0f);   //  (y - y0f)

        const float wa = __fmul_rn(dx1, dy1);
        const float wb = __fmul_rn(dx1, dy0);
        const float wc = __fmul_rn(dx0, dy1);
        const float wd = __fmul_rn(dx0, dy0);

        // out = ((wa*Ia + wb*Ib) + wc*Ic) + wd*Id, left-to-right, no fma
        const float p1 = __fmul_rn(wa, Ia);
        const float p2 = __fmul_rn(wb, Ib);
        const float p3 = __fmul_rn(wc, Ic);
        const float p4 = __fmul_rn(wd, Id);
        rp[i] = __fadd_rn(__fadd_rn(__fadd_rn(p1, p2), p3), p4);
    }

    reinterpret_cast<float4*>(out + (size_t)n * HW + p)[0] = res;
}

extern "C" void kernel_launch(void* const* d_in, const int* in_sizes, int n_in,
                              void* d_out, int out_size)
{
    const float* stimuli = (const float*)d_in[0];
    const float* eye     = (const float*)d_in[1];
    float* out           = (float*)d_out;

    dim3 block(256);
    dim3 grid((GROUPS_PER_FRAME + 255) / 256, NFRAMES);
    warp_bilinear_kernel<<<grid, block>>>(stimuli, eye, out);
}

// round 3
// speedup vs baseline: 1.0767x; 1.0767x over previous
#include <cuda_runtime.h>
#include <cstdint>

// Fixed problem shape: stimuli [4,32,304,608,1] fp32, eye [4,32,2,3]
constexpr int H  = 304;
constexpr int W  = 608;            // 608 = 19*32 -> warps never straddle rows
constexpr int HW = H * W;          // 184832
constexpr int NFRAMES = 128;       // 4*32
constexpr int THREADS = 256;
constexpr int BLOCKS_X = HW / THREADS;  // 722, exact

__global__ __launch_bounds__(THREADS) void warp_bilinear_kernel(
    const float* __restrict__ stimuli,
    const float* __restrict__ eye,
    float* __restrict__ out)
{
    const int n = blockIdx.y;                                  // frame 0..127
    const int p = blockIdx.x * THREADS + threadIdx.x;          // pixel index
    const int row = p / W;     // compile-time W -> mul/shift
    const int col = p - row * W;

    const float* a = eye + (size_t)n * 6;
    const float a00 = __ldg(a + 0);
    const float a01 = __ldg(a + 1);
    const float a02 = __ldg(a + 2);
    const float a10 = __ldg(a + 3);
    const float a11 = __ldg(a + 4);
    const float a12 = __ldg(a + 5);

    // jnp.linspace(-1,1,n): v[i] = fl(-1 + fl(i*step)), endpoint exactly 1.0
    const float step_y = 2.0f / (float)(H - 1);
    const float step_x = 2.0f / (float)(W - 1);
    const float yt = (row == H - 1) ? 1.0f
                   : __fadd_rn(-1.0f, __fmul_rn((float)row, step_y));
    const float xt = (col == W - 1) ? 1.0f
                   : __fadd_rn(-1.0f, __fmul_rn((float)col, step_x));

    // einsum k-order fmuladd chain: T = fadd(fmaf(a1, yt, fmul(a0, xt)), a2)
    const float Tx = __fadd_rn(__fmaf_rn(a01, yt, __fmul_rn(a00, xt)), a02);
    const float Ty = __fadd_rn(__fmaf_rn(a11, yt, __fmul_rn(a10, xt)), a12);

    const float x = __fmul_rn(__fadd_rn(Tx, 1.0f), (float)W * 0.5f);
    const float y = __fmul_rn(__fadd_rn(Ty, 1.0f), (float)H * 0.5f);

    int x0 = (int)floorf(x);
    int y0 = (int)floorf(y);
    int x1 = x0 + 1;
    int y1 = y0 + 1;
    x0 = min(max(x0, 0), W - 1);
    x1 = min(max(x1, 0), W - 1);
    y0 = min(max(y0, 0), H - 1);
    y1 = min(max(y1, 0), H - 1);

    const float* __restrict__ img = stimuli + (size_t)n * HW;

    const float Ia = __ldg(img + y0 * W + x0);
    const float Ib = __ldg(img + y1 * W + x0);
    const float Ic = __ldg(img + y0 * W + x1);
    const float Id = __ldg(img + y1 * W + x1);

    const float x0f = (float)x0, x1f = (float)x1;
    const float y0f = (float)y0, y1f = (float)y1;

    // weights: separately rounded subs/muls (no fma contraction)
    const float dx1 = __fsub_rn(x1f, x);
    const float dx0 = __fsub_rn(x, x0f);
    const float dy1 = __fsub_rn(y1f, y);
    const float dy0 = __fsub_rn(y, y0f);

    const float wa = __fmul_rn(dx1, dy1);
    const float wb = __fmul_rn(dx1, dy0);
    const float wc = __fmul_rn(dx0, dy1);
    const float wd = __fmul_rn(dx0, dy0);

    // out = ((wa*Ia + wb*Ib) + wc*Ic) + wd*Id, left-to-right, no fma
    const float p1 = __fmul_rn(wa, Ia);
    const float p2 = __fmul_rn(wb, Ib);
    const float p3 = __fmul_rn(wc, Ic);
    const float p4 = __fmul_rn(wd, Id);
    out[(size_t)n * HW + p] = __fadd_rn(__fadd_rn(__fadd_rn(p1, p2), p3), p4);
}

extern "C" void kernel_launch(void* const* d_in, const int* in_sizes, int n_in,
                              void* d_out, int out_size)
{
    const float* stimuli = (const float*)d_in[0];
    const float* eye     = (const float*)d_in[1];
    float* out           = (float*)d_out;

    dim3 block(THREADS);
    dim3 grid(BLOCKS_X, NFRAMES);
    warp_bilinear_kernel<<<grid, block>>>(stimuli, eye, out);
}

// round 4
// speedup vs baseline: 1.4788x; 1.3735x over previous
#include <cuda_runtime.h>
#include <cstdint>

// Fixed shape: stimuli [4,32,304,608,1] fp32, eye [4,32,2,3]
constexpr int H  = 304;
constexpr int W  = 608;            // 608 = 19*32
constexpr int HW = H * W;          // 184832
constexpr int NFRAMES = 128;
constexpr int ROWS_PT = 4;         // rows per thread (H/4 = 76 exact)
constexpr int CGROUPS = W / 32;    // 19 column groups per row-group
constexpr int RGROUPS = H / ROWS_PT;           // 76
constexpr int WARPS_PER_FRAME = RGROUPS * CGROUPS;  // 1444
constexpr int WARPS_PER_BLOCK = 4;             // 128 threads
constexpr int BLOCKS_X = WARPS_PER_FRAME / WARPS_PER_BLOCK;  // 361 exact

__global__ __launch_bounds__(WARPS_PER_BLOCK * 32) void warp_bilinear_kernel(
    const float* __restrict__ stimuli,
    const float* __restrict__ eye,
    float* __restrict__ out)
{
    const int n    = blockIdx.y;
    const int warp = blockIdx.x * WARPS_PER_BLOCK + (threadIdx.x >> 5);
    const int lane = threadIdx.x & 31;

    const int rg  = warp / CGROUPS;          // row group 0..75
    const int cg  = warp - rg * CGROUPS;     // col group 0..18
    const int col = cg * 32 + lane;
    const int r0  = rg * ROWS_PT;

    const float* a = eye + (size_t)n * 6;
    const float a00 = __ldg(a + 0);
    const float a01 = __ldg(a + 1);
    const float a02 = __ldg(a + 2);
    const float a10 = __ldg(a + 3);
    const float a11 = __ldg(a + 4);
    const float a12 = __ldg(a + 5);

    // jnp.linspace(-1,1,n): v[i] = fl(-1 + fl(i*step)), endpoint exactly 1.0
    const float step_x = 2.0f / (float)(W - 1);
    const float step_y = 2.0f / (float)(H - 1);
    const float xt = (col == W - 1) ? 1.0f
                   : __fadd_rn(-1.0f, __fmul_rn((float)col, step_x));

    // Per-thread invariants (col fixed across the 4 rows)
    const float a00xt = __fmul_rn(a00, xt);
    const float a10xt = __fmul_rn(a10, xt);

    const float* __restrict__ img  = stimuli + (size_t)n * HW;
    float* __restrict__       dst  = out     + (size_t)n * HW;

#pragma unroll
    for (int i = 0; i < ROWS_PT; ++i) {
        const int row = r0 + i;
        const float yt = (row == H - 1) ? 1.0f
                       : __fadd_rn(-1.0f, __fmul_rn((float)row, step_y));

        // einsum k-order fmuladd chain: T = fadd(fmaf(a1, yt, a0*xt), a2)
        const float Tx = __fadd_rn(__fmaf_rn(a01, yt, a00xt), a02);
        const float Ty = __fadd_rn(__fmaf_rn(a11, yt, a10xt), a12);

        const float x = __fmul_rn(__fadd_rn(Tx, 1.0f), (float)W * 0.5f);
        const float y = __fmul_rn(__fadd_rn(Ty, 1.0f), (float)H * 0.5f);

        int x0 = (int)floorf(x);
        int y0 = (int)floorf(y);
        int x1 = x0 + 1;
        int y1 = y0 + 1;
        x0 = min(max(x0, 0), W - 1);
        x1 = min(max(x1, 0), W - 1);
        y0 = min(max(y0, 0), H - 1);
        y1 = min(max(y1, 0), H - 1);

        const float Ia = __ldg(img + y0 * W + x0);
        const float Ib = __ldg(img + y1 * W + x0);
        const float Ic = __ldg(img + y0 * W + x1);
        const float Id = __ldg(img + y1 * W + x1);

        const float x0f = (float)x0, x1f = (float)x1;
        const float y0f = (float)y0, y1f = (float)y1;

        // separately rounded subs/muls (no fma contraction) — matches JAX
        const float dx1 = __fsub_rn(x1f, x);
        const float dx0 = __fsub_rn(x, x0f);
        const float dy1 = __fsub_rn(y1f, y);
        const float dy0 = __fsub_rn(y, y0f);

        const float wa = __fmul_rn(dx1, dy1);
        const float wb = __fmul_rn(dx1, dy0);
        const float wc = __fmul_rn(dx0, dy1);
        const float wd = __fmul_rn(dx0, dy0);

        const float p1 = __fmul_rn(wa, Ia);
        const float p2 = __fmul_rn(wb, Ib);
        const float p3 = __fmul_rn(wc, Ic);
        const float p4 = __fmul_rn(wd, Id);
        dst[row * W + col] = __fadd_rn(__fadd_rn(__fadd_rn(p1, p2), p3), p4);
    }
}

extern "C" void kernel_launch(void* const* d_in, const int* in_sizes, int n_in,
                              void* d_out, int out_size)
{
    const float* stimuli = (const float*)d_in[0];
    const float* eye     = (const float*)d_in[1];
    float* out           = (float*)d_out;

    dim3 block(WARPS_PER_BLOCK * 32);
    dim3 grid(BLOCKS_X, NFRAMES);
    warp_bilinear_kernel<<<grid, block>>>(stimuli, eye, out);
}

// round 5
// speedup vs baseline: 1.8128x; 1.2258x over previous
#include <cuda_runtime.h>
#include <cstdint>

// Fixed shape: stimuli [4,32,304,608,1] fp32, eye [4,32,2,3]
constexpr int H  = 304;
constexpr int W  = 608;
constexpr int HW = H * W;            // 184832
constexpr int NFRAMES = 128;

// Warp output tile: 8 cols x 4 rows per iteration, 4 iterations -> 8x16 px.
constexpr int TCOLS = 8;
constexpr int TROWS = 4;
constexpr int ITERS = 4;
constexpr int COL_TILES = W / TCOLS;               // 76
constexpr int ROW_TILES = H / (TROWS * ITERS);     // 19
constexpr int WARPS_PER_FRAME = COL_TILES * ROW_TILES;  // 1444
constexpr int WARPS_PER_BLOCK = 4;                 // 128 threads
constexpr int BLOCKS_X = WARPS_PER_FRAME / WARPS_PER_BLOCK;  // 361 exact

__global__ __launch_bounds__(WARPS_PER_BLOCK * 32) void warp_bilinear_kernel(
    const float* __restrict__ stimuli,
    const float* __restrict__ eye,
    float* __restrict__ out)
{
    const int n    = blockIdx.y;
    const int warp = blockIdx.x * WARPS_PER_BLOCK + (threadIdx.x >> 5);
    const int lane = threadIdx.x & 31;

    const int rt = warp / COL_TILES;                // row tile 0..18
    const int ct = warp - rt * COL_TILES;           // col tile 0..75

    const int col  = ct * TCOLS + (lane & (TCOLS - 1));       // fixed per thread
    const int rbase = rt * (TROWS * ITERS) + (lane >> 3);     // starting row

    const float* a = eye + (size_t)n * 6;
    const float a00 = __ldg(a + 0);
    const float a01 = __ldg(a + 1);
    const float a02 = __ldg(a + 2);
    const float a10 = __ldg(a + 3);
    const float a11 = __ldg(a + 4);
    const float a12 = __ldg(a + 5);

    // jnp.linspace(-1,1,n): v[i] = fl(-1 + fl(i*step)), endpoint exactly 1.0
    const float step_x = 2.0f / (float)(W - 1);
    const float step_y = 2.0f / (float)(H - 1);
    const float xt = (col == W - 1) ? 1.0f
                   : __fadd_rn(-1.0f, __fmul_rn((float)col, step_x));

    // Per-thread invariants (col fixed across all rows)
    const float a00xt = __fmul_rn(a00, xt);
    const float a10xt = __fmul_rn(a10, xt);

    const float* __restrict__ img = stimuli + (size_t)n * HW;
    float* __restrict__       dst = out     + (size_t)n * HW;

#pragma unroll
    for (int i = 0; i < ITERS; ++i) {
        const int row = rbase + i * TROWS;
        const float yt = (row == H - 1) ? 1.0f
                       : __fadd_rn(-1.0f, __fmul_rn((float)row, step_y));

        // einsum k-order fmuladd chain: T = fadd(fmaf(a1, yt, a0*xt), a2)
        const float Tx = __fadd_rn(__fmaf_rn(a01, yt, a00xt), a02);
        const float Ty = __fadd_rn(__fmaf_rn(a11, yt, a10xt), a12);

        const float x = __fmul_rn(__fadd_rn(Tx, 1.0f), (float)W * 0.5f);
        const float y = __fmul_rn(__fadd_rn(Ty, 1.0f), (float)H * 0.5f);

        int x0 = (int)floorf(x);
        int y0 = (int)floorf(y);
        int x1 = x0 + 1;
        int y1 = y0 + 1;
        x0 = min(max(x0, 0), W - 1);
        x1 = min(max(x1, 0), W - 1);
        y0 = min(max(y0, 0), H - 1);
        y1 = min(max(y1, 0), H - 1);

        const float Ia = __ldg(img + y0 * W + x0);
        const float Ib = __ldg(img + y1 * W + x0);
        const float Ic = __ldg(img + y0 * W + x1);
        const float Id = __ldg(img + y1 * W + x1);

        const float x0f = (float)x0, x1f = (float)x1;
        const float y0f = (float)y0, y1f = (float)y1;

        // separately rounded subs/muls (no fma contraction) — matches JAX
        const float dx1 = __fsub_rn(x1f, x);
        const float dx0 = __fsub_rn(x, x0f);
        const float dy1 = __fsub_rn(y1f, y);
        const float dy0 = __fsub_rn(y, y0f);

        const float wa = __fmul_rn(dx1, dy1);
        const float wb = __fmul_rn(dx1, dy0);
        const float wc = __fmul_rn(dx0, dy1);
        const float wd = __fmul_rn(dx0, dy0);

        const float p1 = __fmul_rn(wa, Ia);
        const float p2 = __fmul_rn(wb, Ib);
        const float p3 = __fmul_rn(wc, Ic);
        const float p4 = __fmul_rn(wd, Id);
        dst[row * W + col] = __fadd_rn(__fadd_rn(__fadd_rn(p1, p2), p3), p4);
    }
}

extern "C" void kernel_launch(void* const* d_in, const int* in_sizes, int n_in,
                              void* d_out, int out_size)
{
    const float* stimuli = (const float*)d_in[0];
    const float* eye     = (const float*)d_in[1];
    float* out           = (float*)d_out;

    dim3 block(WARPS_PER_BLOCK * 32);
    dim3 grid(BLOCKS_X, NFRAMES);
    warp_bilinear_kernel<<<grid, block>>>(stimuli, eye, out);
}